// round 7
// baseline (speedup 1.0000x reference)
#include <cuda_runtime.h>
#include <cuda_bf16.h>
#include <cstdint>

#define BSZ     4
#define D_MODEL 1024
#define QLEN    512
#define MLEN    512
#define KLEN    1024
#define NHEAD   16
#define DHEAD   64
#define DINNER  4096

typedef __nv_bfloat16 bf16;

// ---------------- fp32 scratch ----------------------------------------------
__device__ float g_wheads[BSZ * 3 * D_MODEL * KLEN];       // 48 MB
__device__ float g_rk[D_MODEL * KLEN];                     // 4 MB
__device__ float g_tmp1[BSZ * D_MODEL * QLEN];             // 8 MB
__device__ float g_x[BSZ * D_MODEL * QLEN];                // 8 MB
__device__ float g_tmp2[BSZ * D_MODEL * QLEN];             // 8 MB

// ---------------- bf16-split (hi,hi,lo / hi,lo,hi) scratch -------------------
__device__ bf16 g_qkvw3[3 * D_MODEL * 3 * D_MODEL];
__device__ bf16 g_rw3  [D_MODEL * 3 * D_MODEL];
__device__ bf16 g_ow3  [D_MODEL * 3 * D_MODEL];
__device__ bf16 g_ff1w3[DINNER * 3 * D_MODEL];
__device__ bf16 g_ff2w3[D_MODEL * 3 * DINNER];
__device__ bf16 g_pos3 [3 * D_MODEL * KLEN];
__device__ bf16 g_cat3 [BSZ * 3 * D_MODEL * KLEN];
__device__ bf16 g_avec3[BSZ * 3 * D_MODEL * QLEN];
__device__ bf16 g_x3   [BSZ * 3 * D_MODEL * QLEN];
__device__ bf16 g_h3   [BSZ * 3 * DINNER * QLEN];

// ---------------- helpers ----------------------------------------------------
__device__ __forceinline__ void split_bf16(float x, bf16& hi, bf16& lo)
{
    hi = __float2bfloat16(x);
    lo = __float2bfloat16(x - __bfloat162float(hi));
}

__device__ __forceinline__ void cp_async16(uint32_t smem_dst, const void* gmem_src)
{
    asm volatile("cp.async.cg.shared.global [%0], [%1], 16;\n"
                 :: "r"(smem_dst), "l"(gmem_src));
}
__device__ __forceinline__ void cp_commit()
{
    asm volatile("cp.async.commit_group;\n");
}
__device__ __forceinline__ void cp_wait_all()
{
    asm volatile("cp.async.wait_group 0;\n");
}
__device__ __forceinline__ void ldsm_x4(uint32_t& r0, uint32_t& r1, uint32_t& r2, uint32_t& r3, uint32_t addr)
{
    asm volatile("ldmatrix.sync.aligned.m8n8.x4.shared.b16 {%0,%1,%2,%3}, [%4];\n"
                 : "=r"(r0), "=r"(r1), "=r"(r2), "=r"(r3) : "r"(addr));
}
__device__ __forceinline__ void ldsm_x4_t(uint32_t& r0, uint32_t& r1, uint32_t& r2, uint32_t& r3, uint32_t addr)
{
    asm volatile("ldmatrix.sync.aligned.m8n8.x4.trans.shared.b16 {%0,%1,%2,%3}, [%4];\n"
                 : "=r"(r0), "=r"(r1), "=r"(r2), "=r"(r3) : "r"(addr));
}
__device__ __forceinline__ void mma16816(float* c, const uint32_t* a, const uint32_t* b)
{
    asm volatile(
        "mma.sync.aligned.m16n8k16.row.col.f32.bf16.bf16.f32 "
        "{%0,%1,%2,%3}, {%4,%5,%6,%7}, {%8,%9}, {%0,%1,%2,%3};\n"
        : "+f"(c[0]), "+f"(c[1]), "+f"(c[2]), "+f"(c[3])
        : "r"(a[0]), "r"(a[1]), "r"(a[2]), "r"(a[3]), "r"(b[0]), "r"(b[1]));
}

// ---------------- expansion kernels ------------------------------------------
__global__ void expandA_kernel(const float* __restrict__ in, bf16* __restrict__ out, int K)
{
    int k = blockIdx.x * 256 + threadIdx.x;
    int m = blockIdx.y;
    float x = in[(long)m * K + k];
    bf16 hi, lo; split_bf16(x, hi, lo);
    bf16* o = out + (long)m * 3 * K + 3 * k;
    o[0] = hi; o[1] = hi; o[2] = lo;
}

// B-pattern with column offset n0 (row stride ldn)
__global__ void expandB_kernel(const float* __restrict__ in, bf16* __restrict__ out,
                               int ldn, int n0, long sIn, long sOut)
{
    int n = n0 + blockIdx.x * 256 + threadIdx.x;
    int k = blockIdx.y;
    float x = in[(long)blockIdx.z * sIn + (long)k * ldn + n];
    bf16 hi, lo; split_bf16(x, hi, lo);
    bf16* o = out + (long)blockIdx.z * sOut + (long)(3 * k) * ldn + n;
    o[0] = hi; o[ldn] = lo; o[2 * ldn] = hi;
}

// cat expansion with time offset t0base (cols < 256 provably unused)
__global__ void expand_cat_kernel(const float* __restrict__ z0, const float* __restrict__ z1ss,
                                  int t0base)
{
    int t = t0base + blockIdx.x * 256 + threadIdx.x;
    int d = blockIdx.y;
    int b = blockIdx.z;
    float x = (t < MLEN) ? z0[((long)b * D_MODEL + d) * MLEN + t]
                         : z1ss[((long)b * D_MODEL + d) * QLEN + (t - MLEN)];
    bf16 hi, lo; split_bf16(x, hi, lo);
    bf16* o = g_cat3 + (long)b * 3 * D_MODEL * KLEN + (long)(3 * d) * KLEN + t;
    o[0] = hi; o[KLEN] = lo; o[2 * KLEN] = hi;
}

// ---------------- tensor-core GEMM (mma.sync) --------------------------------
// C = A(MxK) * B(KxN window)  [+bias][+addend]
// mode: 0 = fp32 out, 1 = fp32 relu out, 2 = bf16-split([hi,lo,hi] rows) relu out
#define GBM 128
#define GBN 128
#define GBK 32
#define APAD 40
#define BPAD 136

__global__ __launch_bounds__(256)
void gemm_bf16_kernel(const bf16* __restrict__ A,
                      const bf16* __restrict__ B,
                      void*       __restrict__ Cv,
                      const float* __restrict__ bias,
                      const float* __restrict__ addend,
                      int M, int K, int ldn,
                      long strideB, long strideC, long strideAdd,
                      int mode)
{
    __shared__ bf16 As[2][GBM * APAD];
    __shared__ bf16 Bs[2][GBK * BPAD];

    const int tid  = threadIdx.x;
    const int lane = tid & 31;
    const int warp = tid >> 5;
    const int wm = warp >> 2;
    const int wn = warp & 3;
    const int bn = blockIdx.x * GBN;
    const int bm = blockIdx.y * GBM;

    const bf16* Ag = A + (long)bm * K;
    const bf16* Bg = B + (long)blockIdx.z * strideB;

    uint32_t sA = (uint32_t)__cvta_generic_to_shared(&As[0][0]);
    uint32_t sB = (uint32_t)__cvta_generic_to_shared(&Bs[0][0]);
    const uint32_t sAsz = GBM * APAD * 2;
    const uint32_t sBsz = GBK * BPAD * 2;

    float acc[4][4][4];
#pragma unroll
    for (int i = 0; i < 4; i++)
#pragma unroll
        for (int j = 0; j < 4; j++)
#pragma unroll
            for (int r = 0; r < 4; r++) acc[i][j][r] = 0.f;

    auto load_tiles = [&](int buf, int k0) {
#pragma unroll
        for (int i = 0; i < 2; i++) {
            int c   = tid + 256 * i;
            int row = c >> 2, ch = c & 3;
            cp_async16(sA + buf * sAsz + (row * APAD + ch * 8) * 2,
                       Ag + (long)row * K + k0 + ch * 8);
        }
#pragma unroll
        for (int i = 0; i < 2; i++) {
            int c   = tid + 256 * i;
            int row = c >> 4, ch = c & 15;
            cp_async16(sB + buf * sBsz + (row * BPAD + ch * 8) * 2,
                       Bg + (long)(k0 + row) * ldn + bn + ch * 8);
        }
        cp_commit();
    };

    load_tiles(0, 0);

    const int nIter = K / GBK;
    for (int it = 0; it < nIter; it++) {
        int buf = it & 1;
        cp_wait_all();
        __syncthreads();
        if (it + 1 < nIter) load_tiles(buf ^ 1, (it + 1) * GBK);

#pragma unroll
        for (int ks = 0; ks < 2; ks++) {
            uint32_t afrag[4][4];
            uint32_t bfrag[4][2];
            int lrow = lane & 15, lcol = (lane >> 4) * 8;
#pragma unroll
            for (int mi = 0; mi < 4; mi++) {
                uint32_t addr = sA + buf * sAsz +
                    ((64 * wm + 16 * mi + lrow) * APAD + ks * 16 + lcol) * 2;
                ldsm_x4(afrag[mi][0], afrag[mi][1], afrag[mi][2], afrag[mi][3], addr);
            }
#pragma unroll
            for (int nj2 = 0; nj2 < 2; nj2++) {
                uint32_t addr = sB + buf * sBsz +
                    ((ks * 16 + lrow) * BPAD + 32 * wn + 16 * nj2 + lcol) * 2;
                uint32_t r0, r1, r2, r3;
                ldsm_x4_t(r0, r1, r2, r3, addr);
                bfrag[2 * nj2][0] = r0;     bfrag[2 * nj2][1] = r1;
                bfrag[2 * nj2 + 1][0] = r2; bfrag[2 * nj2 + 1][1] = r3;
            }
#pragma unroll
            for (int mi = 0; mi < 4; mi++)
#pragma unroll
                for (int nj = 0; nj < 4; nj++)
                    mma16816(acc[mi][nj], afrag[mi], bfrag[nj]);
        }
        __syncthreads();
    }

    const float* Ad = addend ? (addend + (long)blockIdx.z * strideAdd) : nullptr;
    int g = lane >> 2, tg = lane & 3;

    if (mode == 2) {
        // bf16-split B-pattern output (rows 3m hi, 3m+1 lo, 3m+2 hi) + relu
        bf16* C3 = (bf16*)Cv + (long)blockIdx.z * strideC;
#pragma unroll
        for (int mi = 0; mi < 4; mi++) {
            int row0 = bm + 64 * wm + 16 * mi + g;
            int row1 = row0 + 8;
            float bv0 = bias ? bias[row0] : 0.f;
            float bv1 = bias ? bias[row1] : 0.f;
#pragma unroll
            for (int nj = 0; nj < 4; nj++) {
                int col = bn + 32 * wn + 8 * nj + 2 * tg;
#pragma unroll
                for (int half = 0; half < 2; half++) {
                    int row = half ? row1 : row0;
                    float bv = half ? bv1 : bv0;
                    float v0 = fmaxf(acc[mi][nj][2 * half]     + bv, 0.f);
                    float v1 = fmaxf(acc[mi][nj][2 * half + 1] + bv, 0.f);
                    bf16 h0, l0, h1, l1;
                    split_bf16(v0, h0, l0);
                    split_bf16(v1, h1, l1);
                    long base = (long)(3 * row) * ldn + col;
                    C3[base]               = h0; C3[base + 1]           = h1;
                    C3[base + ldn]         = l0; C3[base + ldn + 1]     = l1;
                    C3[base + 2 * ldn]     = h0; C3[base + 2 * ldn + 1] = h1;
                }
            }
        }
        return;
    }

    float* Cb = (float*)Cv + (long)blockIdx.z * strideC;
#pragma unroll
    for (int mi = 0; mi < 4; mi++) {
        int row0 = bm + 64 * wm + 16 * mi + g;
        int row1 = row0 + 8;
        float bv0 = bias ? bias[row0] : 0.f;
        float bv1 = bias ? bias[row1] : 0.f;
#pragma unroll
        for (int nj = 0; nj < 4; nj++) {
            int col = bn + 32 * wn + 8 * nj + 2 * tg;
            float v00 = acc[mi][nj][0] + bv0;
            float v01 = acc[mi][nj][1] + bv0;
            float v10 = acc[mi][nj][2] + bv1;
            float v11 = acc[mi][nj][3] + bv1;
            if (Ad) {
                v00 += Ad[(long)row0 * ldn + col];
                v01 += Ad[(long)row0 * ldn + col + 1];
                v10 += Ad[(long)row1 * ldn + col];
                v11 += Ad[(long)row1 * ldn + col + 1];
            }
            if (mode == 1) {
                v00 = fmaxf(v00, 0.f); v01 = fmaxf(v01, 0.f);
                v10 = fmaxf(v10, 0.f); v11 = fmaxf(v11, 0.f);
            }
            Cb[(long)row0 * ldn + col]     = v00;
            Cb[(long)row0 * ldn + col + 1] = v01;
            Cb[(long)row1 * ldn + col]     = v10;
            Cb[(long)row1 * ldn + col + 1] = v11;
        }
    }
}

// ---------------- tiled banded attention (writes bf16-split avec3) -----------
#define AT_SMEM ((64*65*2 + 64*258 + 64*260 + 4*64 + 64) * 4)

__global__ __launch_bounds__(256)
void attn_tiled_kernel(const float* __restrict__ wheads,
                       const float* __restrict__ rk,
                       const float* __restrict__ rwb,
                       const float* __restrict__ rrb,
                       bf16*        __restrict__ avec3)
{
    extern __shared__ float sm[];
    float* qw   = sm;                       // [qi][d]  stride 65
    float* qr   = qw  + 64 * 65;            // [qi][d]  stride 65
    float* BDs  = qr  + 64 * 65;            // [qi][t]  stride 258
    float* U    = BDs + 64 * 258;
    float* red  = U   + 64 * 260;
    float* sinv = red + 4 * 64;
    float* Rs = U;                          // [d][t]   stride 260 (phase 1)
    float* Ks = U;                          // [jj][d]  stride 65  (phase 2)
    float* Vs = U + 64 * 65;                // [jj][d]  stride 65
    float* Ps = U + 2 * 64 * 65;            // [qi][jj] stride 65

    const int i0 = blockIdx.x * 64;
    const int h  = blockIdx.y;
    const int b  = blockIdx.z;
    const int tid = threadIdx.x;

    const float* W  = wheads + (long)b * (3 * D_MODEL) * KLEN;
    const float* Qg = W + (long)(h * DHEAD) * KLEN;
    const float* Kg = W + (long)(D_MODEL + h * DHEAD) * KLEN;
    const float* Vg = W + (long)(2 * D_MODEL + h * DHEAD) * KLEN;

    for (int idx = tid; idx < 64 * 64; idx += 256) {
        int d = idx >> 6, q = idx & 63;
        float qv = Qg[(long)d * KLEN + MLEN + i0 + q];
        qw[q * 65 + d] = qv + rwb[h * DHEAD + d];
        qr[q * 65 + d] = qv + rrb[h * DHEAD + d];
    }
    for (int idx = tid; idx < 64 * 256; idx += 256) {
        int d = idx >> 8, t = idx & 255;
        Rs[d * 260 + t] = rk[(long)(h * DHEAD + d) * KLEN + 768 + t];
    }
    __syncthreads();

    {
        int q = tid & 63, tg = tid >> 6;
        for (int tt = 0; tt < 64; tt++) {
            int t = tg * 64 + tt;
            float acc = 0.f;
#pragma unroll 16
            for (int d = 0; d < 64; d++)
                acc += qr[q * 65 + d] * Rs[d * 260 + t];
            BDs[q * 258 + t] = acc;
        }
    }

    const int qi = tid & 63;
    const int jg = tid >> 6;
    float O[16];
#pragma unroll
    for (int u = 0; u < 16; u++) O[u] = 0.f;
    float sume = 0.f;

    for (int c = 0; c < 5; c++) {
        int jb = c * 64;
        __syncthreads();
        for (int idx = tid; idx < 64 * 64; idx += 256) {
            int d = idx >> 6, jj = idx & 63;
            int jglob = i0 + 257 + jb + jj;
            float kv = 0.f, vv = 0.f;
            if (jglob < KLEN) {
                kv = Kg[(long)d * KLEN + jglob];
                vv = Vg[(long)d * KLEN + jglob];
            }
            Ks[jj * 65 + d] = kv;
            Vs[jj * 65 + d] = vv;
        }
        __syncthreads();

        {
            float acc[16];
#pragma unroll
            for (int u = 0; u < 16; u++) acc[u] = 0.f;
#pragma unroll 8
            for (int d = 0; d < 64; d++) {
                float qv = qw[qi * 65 + d];
#pragma unroll
                for (int u = 0; u < 16; u++)
                    acc[u] += qv * Ks[(jg * 16 + u) * 65 + d];
            }
#pragma unroll
            for (int u = 0; u < 16; u++) {
                int jp = jb + jg * 16 + u;
                int t  = jp - qi;
                float pv = 0.f;
                if (t >= 0 && t < 256)
                    pv = __expf((acc[u] + BDs[qi * 258 + t]) * 0.125f);
                sume += pv;
                Ps[qi * 65 + jg * 16 + u] = pv;
            }
        }
        __syncthreads();

#pragma unroll 4
        for (int jj = 0; jj < 64; jj++) {
            float pv = Ps[qi * 65 + jj];
#pragma unroll
            for (int u = 0; u < 16; u++)
                O[u] += pv * Vs[jj * 65 + jg * 16 + u];
        }
    }

    red[jg * 64 + qi] = sume;
    __syncthreads();
    if (tid < 64)
        sinv[tid] = 1.f / (red[tid] + red[64 + tid] + red[128 + tid] + red[192 + tid]);
    __syncthreads();
    float inv = sinv[qi];
    // write bf16-split B-pattern directly: rows 3d' (hi), 3d'+1 (lo), 3d'+2 (hi)
    bf16* outp = avec3 + (long)b * 3 * D_MODEL * QLEN;
#pragma unroll
    for (int u = 0; u < 16; u++) {
        int dp = h * DHEAD + jg * 16 + u;
        float v = O[u] * inv;
        bf16 hi, lo; split_bf16(v, hi, lo);
        long base = (long)(3 * dp) * QLEN + i0 + qi;
        outp[base]            = hi;
        outp[base + QLEN]     = lo;
        outp[base + 2 * QLEN] = hi;
    }
}

// ---------------- channel LayerNorm (+ optional fused bf16-split out) --------
__global__ __launch_bounds__(256)
void ln_kernel(const float* __restrict__ y, float* __restrict__ out,
               bf16* __restrict__ out3)
{
    int b  = blockIdx.y;
    int t0 = blockIdx.x * 32;
    int tid = threadIdx.x;
    int tt = tid & 31, cg = tid >> 5;
    const float* Y = y + (long)b * D_MODEL * QLEN;

    float s = 0.f, s2 = 0.f;
    for (int c = cg * 128; c < cg * 128 + 128; c++) {
        float v = Y[(long)c * QLEN + t0 + tt];
        s += v; s2 += v * v;
    }
    __shared__ float ssum[8][32], ssq[8][32];
    __shared__ float smean[32], srstd[32];
    ssum[cg][tt] = s; ssq[cg][tt] = s2;
    __syncthreads();
    if (tid < 32) {
        float ts = 0.f, ts2 = 0.f;
#pragma unroll
        for (int g = 0; g < 8; g++) { ts += ssum[g][tid]; ts2 += ssq[g][tid]; }
        float mean = ts * (1.0f / D_MODEL);
        float var  = ts2 * (1.0f / D_MODEL) - mean * mean;
        smean[tid] = mean;
        srstd[tid] = rsqrtf(var + 1e-5f);
    }
    __syncthreads();
    float mean = smean[tt], rstd = srstd[tt];
    float* O = out + (long)b * D_MODEL * QLEN;
    bf16* O3 = out3 ? (out3 + (long)b * 3 * D_MODEL * QLEN) : nullptr;
    for (int c = cg * 128; c < cg * 128 + 128; c++) {
        float v = Y[(long)c * QLEN + t0 + tt];
        float r = (v - mean) * rstd;
        O[(long)c * QLEN + t0 + tt] = r;
        if (O3) {
            bf16 hi, lo; split_bf16(r, hi, lo);
            long base = (long)(3 * c) * QLEN + t0 + tt;
            O3[base]            = hi;
            O3[base + QLEN]     = lo;
            O3[base + 2 * QLEN] = hi;
        }
    }
}

// ---------------- launcher ---------------------------------------------------
extern "C" void kernel_launch(void* const* d_in, const int* in_sizes, int n_in,
                              void* d_out, int out_size)
{
    const float* z1ss    = (const float*)d_in[0];
    const float* uss     = (const float*)d_in[1];
    const float* z0      = (const float*)d_in[2];
    const float* pos_emb = (const float*)d_in[3];
    const float* qkv_w   = (const float*)d_in[4];
    const float* r_w     = (const float*)d_in[5];
    const float* r_w_bias= (const float*)d_in[6];
    const float* r_r_bias= (const float*)d_in[7];
    const float* o_w     = (const float*)d_in[8];
    const float* o_b     = (const float*)d_in[9];
    const float* ff1_w   = (const float*)d_in[10];
    const float* ff1_b   = (const float*)d_in[11];
    const float* ff2_w   = (const float*)d_in[12];
    const float* ff2_b   = (const float*)d_in[13];
    float* out = (float*)d_out;

    float *wheads, *rk, *tmp1, *x, *tmp2;
    bf16 *qkvw3, *rw3, *ow3, *ff1w3, *ff2w3, *pos3, *cat3, *avec3, *x3, *h3;
    cudaGetSymbolAddress((void**)&wheads, g_wheads);
    cudaGetSymbolAddress((void**)&rk,     g_rk);
    cudaGetSymbolAddress((void**)&tmp1,   g_tmp1);
    cudaGetSymbolAddress((void**)&x,      g_x);
    cudaGetSymbolAddress((void**)&tmp2,   g_tmp2);
    cudaGetSymbolAddress((void**)&qkvw3,  g_qkvw3);
    cudaGetSymbolAddress((void**)&rw3,    g_rw3);
    cudaGetSymbolAddress((void**)&ow3,    g_ow3);
    cudaGetSymbolAddress((void**)&ff1w3,  g_ff1w3);
    cudaGetSymbolAddress((void**)&ff2w3,  g_ff2w3);
    cudaGetSymbolAddress((void**)&pos3,   g_pos3);
    cudaGetSymbolAddress((void**)&cat3,   g_cat3);
    cudaGetSymbolAddress((void**)&avec3,  g_avec3);
    cudaGetSymbolAddress((void**)&x3,     g_x3);
    cudaGetSymbolAddress((void**)&h3,     g_h3);

    cudaFuncSetAttribute(attn_tiled_kernel,
                         cudaFuncAttributeMaxDynamicSharedMemorySize, AT_SMEM);

    const long s3dk = (long)3 * D_MODEL * KLEN;   // cat3 / wheads batch stride
    const long s3dq = (long)3 * D_MODEL * QLEN;
    const long sdq  = (long)D_MODEL * QLEN;

    // ---- weight expansions ----
    expandA_kernel<<<dim3(D_MODEL / 256, 3 * D_MODEL), 256>>>(qkv_w, qkvw3, D_MODEL);
    expandA_kernel<<<dim3(D_MODEL / 256, D_MODEL),     256>>>(r_w,   rw3,   D_MODEL);
    expandA_kernel<<<dim3(D_MODEL / 256, D_MODEL),     256>>>(o_w,   ow3,   D_MODEL);
    expandA_kernel<<<dim3(D_MODEL / 256, DINNER),      256>>>(ff1_w, ff1w3, D_MODEL);
    expandA_kernel<<<dim3(DINNER / 256,  D_MODEL),     256>>>(ff2_w, ff2w3, DINNER);

    // pos_emb expansion: only cols [768,1024) used by attention
    expandB_kernel<<<dim3(1, D_MODEL, 1), 256>>>(pos_emb, pos3, KLEN, 768, 0, 0);
    // cat expansion: only cols [256,1024) reachable by Q/K/V usage
    expand_cat_kernel<<<dim3(3, D_MODEL, BSZ), 256>>>(z0, z1ss, 256);

    // ---- QKV, trimmed ----
    // Q rows (0..1023): only cols [512,1024) used
    gemm_bf16_kernel<<<dim3(4, D_MODEL / GBM, BSZ), 256>>>(
        qkvw3, cat3 + 512, wheads + 512, nullptr, uss + 512,
        D_MODEL, 3 * D_MODEL, KLEN, s3dk, s3dk, s3dk, 0);
    // K/V rows (1024..3071): only cols [256,1024) used (band j >= 257)
    gemm_bf16_kernel<<<dim3(6, 2 * D_MODEL / GBM, BSZ), 256>>>(
        qkvw3 + (long)D_MODEL * 3 * D_MODEL, cat3 + 256,
        wheads + (long)D_MODEL * KLEN + 256, nullptr,
        uss + (long)D_MODEL * KLEN + 256,
        2 * D_MODEL, 3 * D_MODEL, KLEN, s3dk, s3dk, s3dk, 0);

    // ---- r_head_k: only cols [768,1024) used ----
    gemm_bf16_kernel<<<dim3(2, D_MODEL / GBM, 1), 256>>>(
        rw3, pos3 + 768, rk + 768, nullptr, nullptr,
        D_MODEL, 3 * D_MODEL, KLEN, 0, 0, 0, 0);

    // ---- tiled banded attention -> avec3 (bf16 split, fused) ----
    attn_tiled_kernel<<<dim3(QLEN / 64, NHEAD, BSZ), 256, AT_SMEM>>>(
        wheads, rk, r_w_bias, r_r_bias, avec3);

    // ---- O-proj: tmp1 = o_w @ avec + o_b + z1ss ----
    gemm_bf16_kernel<<<dim3(QLEN / GBN, D_MODEL / GBM, BSZ), 256>>>(
        ow3, avec3, tmp1, o_b, z1ss,
        D_MODEL, 3 * D_MODEL, QLEN, s3dq, sdq, sdq, 0);

    // ---- x = LN(tmp1), fused x3 ----
    ln_kernel<<<dim3(QLEN / 32, BSZ), 256>>>(tmp1, x, x3);

    // ---- FF1: h3 = split(relu(ff1_w @ x + ff1_b)) fused epilogue ----
    gemm_bf16_kernel<<<dim3(QLEN / GBN, DINNER / GBM, BSZ), 256>>>(
        ff1w3, x3, h3, ff1_b, nullptr,
        DINNER, 3 * D_MODEL, QLEN, s3dq, (long)3 * DINNER * QLEN, 0, 2);

    // ---- FF2: tmp2 = ff2_w @ h + ff2_b + x ----
    gemm_bf16_kernel<<<dim3(QLEN / GBN, D_MODEL / GBM, BSZ), 256>>>(
        ff2w3, h3, tmp2, ff2_b, x,
        D_MODEL, 3 * DINNER, QLEN, (long)3 * DINNER * QLEN, sdq, sdq, 0);

    // ---- out = LN(tmp2) ----
    ln_kernel<<<dim3(QLEN / 32, BSZ), 256>>>(tmp2, out, nullptr);
}

// round 8
// speedup vs baseline: 1.0277x; 1.0277x over previous
#include <cuda_runtime.h>
#include <cuda_bf16.h>
#include <cstdint>

#define BSZ     4
#define D_MODEL 1024
#define QLEN    512
#define MLEN    512
#define KLEN    1024
#define NHEAD   16
#define DHEAD   64
#define DINNER  4096

typedef __nv_bfloat16 bf16;

// ---------------- fp32 scratch ----------------------------------------------
__device__ float g_wheads[BSZ * 3 * D_MODEL * KLEN];       // 48 MB
__device__ float g_rk[D_MODEL * KLEN];                     // 4 MB
__device__ float g_tmp1[BSZ * D_MODEL * QLEN];             // 8 MB
__device__ float g_x[BSZ * D_MODEL * QLEN];                // 8 MB
__device__ float g_tmp2[BSZ * D_MODEL * QLEN];             // 8 MB

// ---------------- bf16-split (hi,hi,lo / hi,lo,hi) scratch -------------------
__device__ bf16 g_qkvw3[3 * D_MODEL * 3 * D_MODEL];
__device__ bf16 g_rw3  [D_MODEL * 3 * D_MODEL];
__device__ bf16 g_ow3  [D_MODEL * 3 * D_MODEL];
__device__ bf16 g_ff1w3[DINNER * 3 * D_MODEL];
__device__ bf16 g_ff2w3[D_MODEL * 3 * DINNER];
__device__ bf16 g_pos3 [3 * D_MODEL * KLEN];
__device__ bf16 g_cat3 [BSZ * 3 * D_MODEL * KLEN];
__device__ bf16 g_avec3[BSZ * 3 * D_MODEL * QLEN];
__device__ bf16 g_x3   [BSZ * 3 * D_MODEL * QLEN];
__device__ bf16 g_h3   [BSZ * 3 * DINNER * QLEN];

// ---------------- helpers ----------------------------------------------------
__device__ __forceinline__ void split_bf16(float x, bf16& hi, bf16& lo)
{
    hi = __float2bfloat16(x);
    lo = __float2bfloat16(x - __bfloat162float(hi));
}

__device__ __forceinline__ void cp_async16(uint32_t smem_dst, const void* gmem_src)
{
    asm volatile("cp.async.cg.shared.global [%0], [%1], 16;\n"
                 :: "r"(smem_dst), "l"(gmem_src));
}
__device__ __forceinline__ void cp_commit()
{
    asm volatile("cp.async.commit_group;\n");
}
__device__ __forceinline__ void cp_wait_all()
{
    asm volatile("cp.async.wait_group 0;\n");
}
__device__ __forceinline__ void ldsm_x4(uint32_t& r0, uint32_t& r1, uint32_t& r2, uint32_t& r3, uint32_t addr)
{
    asm volatile("ldmatrix.sync.aligned.m8n8.x4.shared.b16 {%0,%1,%2,%3}, [%4];\n"
                 : "=r"(r0), "=r"(r1), "=r"(r2), "=r"(r3) : "r"(addr));
}
__device__ __forceinline__ void ldsm_x4_t(uint32_t& r0, uint32_t& r1, uint32_t& r2, uint32_t& r3, uint32_t addr)
{
    asm volatile("ldmatrix.sync.aligned.m8n8.x4.trans.shared.b16 {%0,%1,%2,%3}, [%4];\n"
                 : "=r"(r0), "=r"(r1), "=r"(r2), "=r"(r3) : "r"(addr));
}
__device__ __forceinline__ void mma16816(float* c, const uint32_t* a, const uint32_t* b)
{
    asm volatile(
        "mma.sync.aligned.m16n8k16.row.col.f32.bf16.bf16.f32 "
        "{%0,%1,%2,%3}, {%4,%5,%6,%7}, {%8,%9}, {%0,%1,%2,%3};\n"
        : "+f"(c[0]), "+f"(c[1]), "+f"(c[2]), "+f"(c[3])
        : "r"(a[0]), "r"(a[1]), "r"(a[2]), "r"(a[3]), "r"(b[0]), "r"(b[1]));
}

// ---------------- expansion kernels ------------------------------------------
__global__ void expandA_kernel(const float* __restrict__ in, bf16* __restrict__ out, int K)
{
    int k = blockIdx.x * 256 + threadIdx.x;
    int m = blockIdx.y;
    float x = in[(long)m * K + k];
    bf16 hi, lo; split_bf16(x, hi, lo);
    bf16* o = out + (long)m * 3 * K + 3 * k;
    o[0] = hi; o[1] = hi; o[2] = lo;
}

// B-pattern with column offset n0 (row stride ldn)
__global__ void expandB_kernel(const float* __restrict__ in, bf16* __restrict__ out,
                               int ldn, int n0, long sIn, long sOut)
{
    int n = n0 + blockIdx.x * 256 + threadIdx.x;
    int k = blockIdx.y;
    float x = in[(long)blockIdx.z * sIn + (long)k * ldn + n];
    bf16 hi, lo; split_bf16(x, hi, lo);
    bf16* o = out + (long)blockIdx.z * sOut + (long)(3 * k) * ldn + n;
    o[0] = hi; o[ldn] = lo; o[2 * ldn] = hi;
}

// cat expansion with time offset t0base (cols < 256 provably unused)
__global__ void expand_cat_kernel(const float* __restrict__ z0, const float* __restrict__ z1ss,
                                  int t0base)
{
    int t = t0base + blockIdx.x * 256 + threadIdx.x;
    int d = blockIdx.y;
    int b = blockIdx.z;
    float x = (t < MLEN) ? z0[((long)b * D_MODEL + d) * MLEN + t]
                         : z1ss[((long)b * D_MODEL + d) * QLEN + (t - MLEN)];
    bf16 hi, lo; split_bf16(x, hi, lo);
    bf16* o = g_cat3 + (long)b * 3 * D_MODEL * KLEN + (long)(3 * d) * KLEN + t;
    o[0] = hi; o[KLEN] = lo; o[2 * KLEN] = hi;
}

// ---------------- tensor-core GEMM (mma.sync) --------------------------------
// C = A(MxK) * B(KxN window)  [+bias][+addend]
// mode: 0 = fp32 out, 1 = fp32 relu out, 2 = bf16-split([hi,lo,hi] rows) relu out
#define GBM 128
#define GBN 128
#define GBK 32
#define APAD 40
#define BPAD 136

__global__ __launch_bounds__(256, 2)
void gemm_bf16_kernel(const bf16* __restrict__ A,
                      const bf16* __restrict__ B,
                      void*       __restrict__ Cv,
                      const float* __restrict__ bias,
                      const float* __restrict__ addend,
                      int M, int K, int ldn,
                      long strideB, long strideC, long strideAdd,
                      int mode)
{
    __shared__ bf16 As[2][GBM * APAD];
    __shared__ bf16 Bs[2][GBK * BPAD];

    const int tid  = threadIdx.x;
    const int lane = tid & 31;
    const int warp = tid >> 5;
    const int wm = warp >> 2;
    const int wn = warp & 3;
    const int bn = blockIdx.x * GBN;
    const int bm = blockIdx.y * GBM;

    const bf16* Ag = A + (long)bm * K;
    const bf16* Bg = B + (long)blockIdx.z * strideB;

    uint32_t sA = (uint32_t)__cvta_generic_to_shared(&As[0][0]);
    uint32_t sB = (uint32_t)__cvta_generic_to_shared(&Bs[0][0]);
    const uint32_t sAsz = GBM * APAD * 2;
    const uint32_t sBsz = GBK * BPAD * 2;

    float acc[4][4][4];
#pragma unroll
    for (int i = 0; i < 4; i++)
#pragma unroll
        for (int j = 0; j < 4; j++)
#pragma unroll
            for (int r = 0; r < 4; r++) acc[i][j][r] = 0.f;

    auto load_tiles = [&](int buf, int k0) {
#pragma unroll
        for (int i = 0; i < 2; i++) {
            int c   = tid + 256 * i;
            int row = c >> 2, ch = c & 3;
            cp_async16(sA + buf * sAsz + (row * APAD + ch * 8) * 2,
                       Ag + (long)row * K + k0 + ch * 8);
        }
#pragma unroll
        for (int i = 0; i < 2; i++) {
            int c   = tid + 256 * i;
            int row = c >> 4, ch = c & 15;
            cp_async16(sB + buf * sBsz + (row * BPAD + ch * 8) * 2,
                       Bg + (long)(k0 + row) * ldn + bn + ch * 8);
        }
        cp_commit();
    };

    load_tiles(0, 0);

    const int nIter = K / GBK;
    for (int it = 0; it < nIter; it++) {
        int buf = it & 1;
        cp_wait_all();
        __syncthreads();
        if (it + 1 < nIter) load_tiles(buf ^ 1, (it + 1) * GBK);

#pragma unroll
        for (int ks = 0; ks < 2; ks++) {
            uint32_t afrag[4][4];
            uint32_t bfrag[4][2];
            int lrow = lane & 15, lcol = (lane >> 4) * 8;
#pragma unroll
            for (int mi = 0; mi < 4; mi++) {
                uint32_t addr = sA + buf * sAsz +
                    ((64 * wm + 16 * mi + lrow) * APAD + ks * 16 + lcol) * 2;
                ldsm_x4(afrag[mi][0], afrag[mi][1], afrag[mi][2], afrag[mi][3], addr);
            }
#pragma unroll
            for (int nj2 = 0; nj2 < 2; nj2++) {
                uint32_t addr = sB + buf * sBsz +
                    ((ks * 16 + lrow) * BPAD + 32 * wn + 16 * nj2 + lcol) * 2;
                uint32_t r0, r1, r2, r3;
                ldsm_x4_t(r0, r1, r2, r3, addr);
                bfrag[2 * nj2][0] = r0;     bfrag[2 * nj2][1] = r1;
                bfrag[2 * nj2 + 1][0] = r2; bfrag[2 * nj2 + 1][1] = r3;
            }
#pragma unroll
            for (int mi = 0; mi < 4; mi++)
#pragma unroll
                for (int nj = 0; nj < 4; nj++)
                    mma16816(acc[mi][nj], afrag[mi], bfrag[nj]);
        }
        __syncthreads();
    }

    const float* Ad = addend ? (addend + (long)blockIdx.z * strideAdd) : nullptr;
    int g = lane >> 2, tg = lane & 3;

    if (mode == 2) {
        // bf16-split B-pattern output (rows 3m hi, 3m+1 lo, 3m+2 hi) + relu
        bf16* C3 = (bf16*)Cv + (long)blockIdx.z * strideC;
#pragma unroll
        for (int mi = 0; mi < 4; mi++) {
            int row0 = bm + 64 * wm + 16 * mi + g;
            int row1 = row0 + 8;
            float bv0 = bias ? bias[row0] : 0.f;
            float bv1 = bias ? bias[row1] : 0.f;
#pragma unroll
            for (int nj = 0; nj < 4; nj++) {
                int col = bn + 32 * wn + 8 * nj + 2 * tg;
#pragma unroll
                for (int half = 0; half < 2; half++) {
                    int row = half ? row1 : row0;
                    float bv = half ? bv1 : bv0;
                    float v0 = fmaxf(acc[mi][nj][2 * half]     + bv, 0.f);
                    float v1 = fmaxf(acc[mi][nj][2 * half + 1] + bv, 0.f);
                    bf16 h0, l0, h1, l1;
                    split_bf16(v0, h0, l0);
                    split_bf16(v1, h1, l1);
                    long base = (long)(3 * row) * ldn + col;
                    C3[base]               = h0; C3[base + 1]           = h1;
                    C3[base + ldn]         = l0; C3[base + ldn + 1]     = l1;
                    C3[base + 2 * ldn]     = h0; C3[base + 2 * ldn + 1] = h1;
                }
            }
        }
        return;
    }

    float* Cb = (float*)Cv + (long)blockIdx.z * strideC;
#pragma unroll
    for (int mi = 0; mi < 4; mi++) {
        int row0 = bm + 64 * wm + 16 * mi + g;
        int row1 = row0 + 8;
        float bv0 = bias ? bias[row0] : 0.f;
        float bv1 = bias ? bias[row1] : 0.f;
#pragma unroll
        for (int nj = 0; nj < 4; nj++) {
            int col = bn + 32 * wn + 8 * nj + 2 * tg;
            float v00 = acc[mi][nj][0] + bv0;
            float v01 = acc[mi][nj][1] + bv0;
            float v10 = acc[mi][nj][2] + bv1;
            float v11 = acc[mi][nj][3] + bv1;
            if (Ad) {
                v00 += Ad[(long)row0 * ldn + col];
                v01 += Ad[(long)row0 * ldn + col + 1];
                v10 += Ad[(long)row1 * ldn + col];
                v11 += Ad[(long)row1 * ldn + col + 1];
            }
            if (mode == 1) {
                v00 = fmaxf(v00, 0.f); v01 = fmaxf(v01, 0.f);
                v10 = fmaxf(v10, 0.f); v11 = fmaxf(v11, 0.f);
            }
            Cb[(long)row0 * ldn + col]     = v00;
            Cb[(long)row0 * ldn + col + 1] = v01;
            Cb[(long)row1 * ldn + col]     = v10;
            Cb[(long)row1 * ldn + col + 1] = v11;
        }
    }
}

// ---------------- tiled banded attention (writes bf16-split avec3) -----------
#define AT_SMEM ((64*65*2 + 64*258 + 64*260 + 4*64 + 64) * 4)

__global__ __launch_bounds__(256)
void attn_tiled_kernel(const float* __restrict__ wheads,
                       const float* __restrict__ rk,
                       const float* __restrict__ rwb,
                       const float* __restrict__ rrb,
                       bf16*        __restrict__ avec3)
{
    extern __shared__ float sm[];
    float* qw   = sm;                       // [qi][d]  stride 65
    float* qr   = qw  + 64 * 65;            // [qi][d]  stride 65
    float* BDs  = qr  + 64 * 65;            // [qi][t]  stride 258
    float* U    = BDs + 64 * 258;
    float* red  = U   + 64 * 260;
    float* sinv = red + 4 * 64;
    float* Rs = U;                          // [d][t]   stride 260 (phase 1)
    float* Ks = U;                          // [jj][d]  stride 65  (phase 2)
    float* Vs = U + 64 * 65;                // [jj][d]  stride 65
    float* Ps = U + 2 * 64 * 65;            // [qi][jj] stride 65

    const int i0 = blockIdx.x * 64;
    const int h  = blockIdx.y;
    const int b  = blockIdx.z;
    const int tid = threadIdx.x;

    const float* W  = wheads + (long)b * (3 * D_MODEL) * KLEN;
    const float* Qg = W + (long)(h * DHEAD) * KLEN;
    const float* Kg = W + (long)(D_MODEL + h * DHEAD) * KLEN;
    const float* Vg = W + (long)(2 * D_MODEL + h * DHEAD) * KLEN;

    for (int idx = tid; idx < 64 * 64; idx += 256) {
        int d = idx >> 6, q = idx & 63;
        float qv = Qg[(long)d * KLEN + MLEN + i0 + q];
        qw[q * 65 + d] = qv + rwb[h * DHEAD + d];
        qr[q * 65 + d] = qv + rrb[h * DHEAD + d];
    }
    for (int idx = tid; idx < 64 * 256; idx += 256) {
        int d = idx >> 8, t = idx & 255;
        Rs[d * 260 + t] = rk[(long)(h * DHEAD + d) * KLEN + 768 + t];
    }
    __syncthreads();

    {
        int q = tid & 63, tg = tid >> 6;
        for (int tt = 0; tt < 64; tt++) {
            int t = tg * 64 + tt;
            float acc = 0.f;
#pragma unroll 16
            for (int d = 0; d < 64; d++)
                acc += qr[q * 65 + d] * Rs[d * 260 + t];
            BDs[q * 258 + t] = acc;
        }
    }

    const int qi = tid & 63;
    const int jg = tid >> 6;
    float O[16];
#pragma unroll
    for (int u = 0; u < 16; u++) O[u] = 0.f;
    float sume = 0.f;

    for (int c = 0; c < 5; c++) {
        int jb = c * 64;
        __syncthreads();
        for (int idx = tid; idx < 64 * 64; idx += 256) {
            int d = idx >> 6, jj = idx & 63;
            int jglob = i0 + 257 + jb + jj;
            float kv = 0.f, vv = 0.f;
            if (jglob < KLEN) {
                kv = Kg[(long)d * KLEN + jglob];
                vv = Vg[(long)d * KLEN + jglob];
            }
            Ks[jj * 65 + d] = kv;
            Vs[jj * 65 + d] = vv;
        }
        __syncthreads();

        {
            float acc[16];
#pragma unroll
            for (int u = 0; u < 16; u++) acc[u] = 0.f;
#pragma unroll 8
            for (int d = 0; d < 64; d++) {
                float qv = qw[qi * 65 + d];
#pragma unroll
                for (int u = 0; u < 16; u++)
                    acc[u] += qv * Ks[(jg * 16 + u) * 65 + d];
            }
#pragma unroll
            for (int u = 0; u < 16; u++) {
                int jp = jb + jg * 16 + u;
                int t  = jp - qi;
                float pv = 0.f;
                if (t >= 0 && t < 256)
                    pv = __expf((acc[u] + BDs[qi * 258 + t]) * 0.125f);
                sume += pv;
                Ps[qi * 65 + jg * 16 + u] = pv;
            }
        }
        __syncthreads();

#pragma unroll 4
        for (int jj = 0; jj < 64; jj++) {
            float pv = Ps[qi * 65 + jj];
#pragma unroll
            for (int u = 0; u < 16; u++)
                O[u] += pv * Vs[jj * 65 + jg * 16 + u];
        }
    }

    red[jg * 64 + qi] = sume;
    __syncthreads();
    if (tid < 64)
        sinv[tid] = 1.f / (red[tid] + red[64 + tid] + red[128 + tid] + red[192 + tid]);
    __syncthreads();
    float inv = sinv[qi];
    bf16* outp = avec3 + (long)b * 3 * D_MODEL * QLEN;
#pragma unroll
    for (int u = 0; u < 16; u++) {
        int dp = h * DHEAD + jg * 16 + u;
        float v = O[u] * inv;
        bf16 hi, lo; split_bf16(v, hi, lo);
        long base = (long)(3 * dp) * QLEN + i0 + qi;
        outp[base]            = hi;
        outp[base + QLEN]     = lo;
        outp[base + 2 * QLEN] = hi;
    }
}

// ---------------- channel LayerNorm (+ optional fused bf16-split out) --------
__global__ __launch_bounds__(256)
void ln_kernel(const float* __restrict__ y, float* __restrict__ out,
               bf16* __restrict__ out3)
{
    int b  = blockIdx.y;
    int t0 = blockIdx.x * 32;
    int tid = threadIdx.x;
    int tt = tid & 31, cg = tid >> 5;
    const float* Y = y + (long)b * D_MODEL * QLEN;

    float s = 0.f, s2 = 0.f;
    for (int c = cg * 128; c < cg * 128 + 128; c++) {
        float v = Y[(long)c * QLEN + t0 + tt];
        s += v; s2 += v * v;
    }
    __shared__ float ssum[8][32], ssq[8][32];
    __shared__ float smean[32], srstd[32];
    ssum[cg][tt] = s; ssq[cg][tt] = s2;
    __syncthreads();
    if (tid < 32) {
        float ts = 0.f, ts2 = 0.f;
#pragma unroll
        for (int g = 0; g < 8; g++) { ts += ssum[g][tid]; ts2 += ssq[g][tid]; }
        float mean = ts * (1.0f / D_MODEL);
        float var  = ts2 * (1.0f / D_MODEL) - mean * mean;
        smean[tid] = mean;
        srstd[tid] = rsqrtf(var + 1e-5f);
    }
    __syncthreads();
    float mean = smean[tt], rstd = srstd[tt];
    float* O = out + (long)b * D_MODEL * QLEN;
    bf16* O3 = out3 ? (out3 + (long)b * 3 * D_MODEL * QLEN) : nullptr;
    for (int c = cg * 128; c < cg * 128 + 128; c++) {
        float v = Y[(long)c * QLEN + t0 + tt];
        float r = (v - mean) * rstd;
        O[(long)c * QLEN + t0 + tt] = r;
        if (O3) {
            bf16 hi, lo; split_bf16(r, hi, lo);
            long base = (long)(3 * c) * QLEN + t0 + tt;
            O3[base]            = hi;
            O3[base + QLEN]     = lo;
            O3[base + 2 * QLEN] = hi;
        }
    }
}

// ---------------- launcher ---------------------------------------------------
extern "C" void kernel_launch(void* const* d_in, const int* in_sizes, int n_in,
                              void* d_out, int out_size)
{
    const float* z1ss    = (const float*)d_in[0];
    const float* uss     = (const float*)d_in[1];
    const float* z0      = (const float*)d_in[2];
    const float* pos_emb = (const float*)d_in[3];
    const float* qkv_w   = (const float*)d_in[4];
    const float* r_w     = (const float*)d_in[5];
    const float* r_w_bias= (const float*)d_in[6];
    const float* r_r_bias= (const float*)d_in[7];
    const float* o_w     = (const float*)d_in[8];
    const float* o_b     = (const float*)d_in[9];
    const float* ff1_w   = (const float*)d_in[10];
    const float* ff1_b   = (const float*)d_in[11];
    const float* ff2_w   = (const float*)d_in[12];
    const float* ff2_b   = (const float*)d_in[13];
    float* out = (float*)d_out;

    float *wheads, *rk, *tmp1, *x, *tmp2;
    bf16 *qkvw3, *rw3, *ow3, *ff1w3, *ff2w3, *pos3, *cat3, *avec3, *x3, *h3;
    cudaGetSymbolAddress((void**)&wheads, g_wheads);
    cudaGetSymbolAddress((void**)&rk,     g_rk);
    cudaGetSymbolAddress((void**)&tmp1,   g_tmp1);
    cudaGetSymbolAddress((void**)&x,      g_x);
    cudaGetSymbolAddress((void**)&tmp2,   g_tmp2);
    cudaGetSymbolAddress((void**)&qkvw3,  g_qkvw3);
    cudaGetSymbolAddress((void**)&rw3,    g_rw3);
    cudaGetSymbolAddress((void**)&ow3,    g_ow3);
    cudaGetSymbolAddress((void**)&ff1w3,  g_ff1w3);
    cudaGetSymbolAddress((void**)&ff2w3,  g_ff2w3);
    cudaGetSymbolAddress((void**)&pos3,   g_pos3);
    cudaGetSymbolAddress((void**)&cat3,   g_cat3);
    cudaGetSymbolAddress((void**)&avec3,  g_avec3);
    cudaGetSymbolAddress((void**)&x3,     g_x3);
    cudaGetSymbolAddress((void**)&h3,     g_h3);

    cudaFuncSetAttribute(attn_tiled_kernel,
                         cudaFuncAttributeMaxDynamicSharedMemorySize, AT_SMEM);

    const long s3dk = (long)3 * D_MODEL * KLEN;   // cat3 / wheads batch stride
    const long s3dq = (long)3 * D_MODEL * QLEN;
    const long sdq  = (long)D_MODEL * QLEN;

    // Launch order arranged so launch #6 (ncu -s 5 -c 1) is the QKV GEMM.
    // [0] qkv weight expansion
    expandA_kernel<<<dim3(D_MODEL / 256, 3 * D_MODEL), 256>>>(qkv_w, qkvw3, D_MODEL);
    // [1] cat expansion (cols [256,1024) only)
    expand_cat_kernel<<<dim3(3, D_MODEL, BSZ), 256>>>(z0, z1ss, 256);
    // [2..4] other expansions (independent)
    expandA_kernel<<<dim3(D_MODEL / 256, D_MODEL),     256>>>(r_w,   rw3,   D_MODEL);
    expandB_kernel<<<dim3(1, D_MODEL, 1), 256>>>(pos_emb, pos3, KLEN, 768, 0, 0);
    expandA_kernel<<<dim3(D_MODEL / 256, D_MODEL),     256>>>(o_w,   ow3,   D_MODEL);

    // [5] QKV, single launch over N-window [256,1024): M=3072, N=768 -> 576 CTAs
    gemm_bf16_kernel<<<dim3(6, 3 * D_MODEL / GBM, BSZ), 256>>>(
        qkvw3, cat3 + 256, wheads + 256, nullptr, uss + 256,
        3 * D_MODEL, 3 * D_MODEL, KLEN, s3dk, s3dk, s3dk, 0);

    // remaining weight expansions (needed later)
    expandA_kernel<<<dim3(D_MODEL / 256, DINNER),      256>>>(ff1_w, ff1w3, D_MODEL);
    expandA_kernel<<<dim3(DINNER / 256,  D_MODEL),     256>>>(ff2_w, ff2w3, DINNER);

    // ---- r_head_k: only cols [768,1024) used ----
    gemm_bf16_kernel<<<dim3(2, D_MODEL / GBM, 1), 256>>>(
        rw3, pos3 + 768, rk + 768, nullptr, nullptr,
        D_MODEL, 3 * D_MODEL, KLEN, 0, 0, 0, 0);

    // ---- tiled banded attention -> avec3 (bf16 split, fused) ----
    attn_tiled_kernel<<<dim3(QLEN / 64, NHEAD, BSZ), 256, AT_SMEM>>>(
        wheads, rk, r_w_bias, r_r_bias, avec3);

    // ---- O-proj: tmp1 = o_w @ avec + o_b + z1ss ----
    gemm_bf16_kernel<<<dim3(QLEN / GBN, D_MODEL / GBM, BSZ), 256>>>(
        ow3, avec3, tmp1, o_b, z1ss,
        D_MODEL, 3 * D_MODEL, QLEN, s3dq, sdq, sdq, 0);

    // ---- x = LN(tmp1), fused x3 ----
    ln_kernel<<<dim3(QLEN / 32, BSZ), 256>>>(tmp1, x, x3);

    // ---- FF1: h3 = split(relu(ff1_w @ x + ff1_b)) fused epilogue ----
    gemm_bf16_kernel<<<dim3(QLEN / GBN, DINNER / GBM, BSZ), 256>>>(
        ff1w3, x3, h3, ff1_b, nullptr,
        DINNER, 3 * D_MODEL, QLEN, s3dq, (long)3 * DINNER * QLEN, 0, 2);

    // ---- FF2: tmp2 = ff2_w @ h + ff2_b + x ----
    gemm_bf16_kernel<<<dim3(QLEN / GBN, D_MODEL / GBM, BSZ), 256>>>(
        ff2w3, h3, tmp2, ff2_b, x,
        D_MODEL, 3 * DINNER, QLEN, (long)3 * DINNER * QLEN, sdq, sdq, 0);

    // ---- out = LN(tmp2) ----
    ln_kernel<<<dim3(QLEN / 32, BSZ), 256>>>(tmp2, out, nullptr);
}

// round 9
// speedup vs baseline: 1.2964x; 1.2615x over previous
#include <cuda_runtime.h>
#include <cuda_bf16.h>
#include <cstdint>

#define BSZ     4
#define D_MODEL 1024
#define QLEN    512
#define MLEN    512
#define KLEN    1024
#define NHEAD   16
#define DHEAD   64
#define DINNER  4096

typedef __nv_bfloat16 bf16;

// ---------------- fp32 scratch ----------------------------------------------
__device__ float g_wheads[BSZ * 3 * D_MODEL * KLEN];
__device__ float g_rk[D_MODEL * KLEN];
__device__ float g_tmp1[BSZ * D_MODEL * QLEN];
__device__ float g_x[BSZ * D_MODEL * QLEN];
__device__ float g_tmp2[BSZ * D_MODEL * QLEN];

// ---------------- bf16-split (hi,hi,lo / hi,lo,hi) scratch -------------------
__device__ bf16 g_qkvw3[3 * D_MODEL * 3 * D_MODEL];
__device__ bf16 g_rw3  [D_MODEL * 3 * D_MODEL];
__device__ bf16 g_ow3  [D_MODEL * 3 * D_MODEL];
__device__ bf16 g_ff1w3[DINNER * 3 * D_MODEL];
__device__ bf16 g_ff2w3[D_MODEL * 3 * DINNER];
__device__ bf16 g_pos3 [3 * D_MODEL * KLEN];
__device__ bf16 g_cat3 [BSZ * 3 * D_MODEL * KLEN];
__device__ bf16 g_avec3[BSZ * 3 * D_MODEL * QLEN];
__device__ bf16 g_x3   [BSZ * 3 * D_MODEL * QLEN];
__device__ bf16 g_h3   [BSZ * 3 * DINNER * QLEN];

// ---------------- helpers ----------------------------------------------------
__device__ __forceinline__ void split_bf16(float x, bf16& hi, bf16& lo)
{
    hi = __float2bfloat16(x);
    lo = __float2bfloat16(x - __bfloat162float(hi));
}

__device__ __forceinline__ void cp_async16(uint32_t smem_dst, const void* gmem_src)
{
    asm volatile("cp.async.cg.shared.global [%0], [%1], 16;\n"
                 :: "r"(smem_dst), "l"(gmem_src));
}
__device__ __forceinline__ void cp_commit()
{
    asm volatile("cp.async.commit_group;\n");
}
__device__ __forceinline__ void cp_wait_all()
{
    asm volatile("cp.async.wait_group 0;\n");
}
__device__ __forceinline__ void ldsm_x4(uint32_t& r0, uint32_t& r1, uint32_t& r2, uint32_t& r3, uint32_t addr)
{
    asm volatile("ldmatrix.sync.aligned.m8n8.x4.shared.b16 {%0,%1,%2,%3}, [%4];\n"
                 : "=r"(r0), "=r"(r1), "=r"(r2), "=r"(r3) : "r"(addr));
}
__device__ __forceinline__ void ldsm_x4_t(uint32_t& r0, uint32_t& r1, uint32_t& r2, uint32_t& r3, uint32_t addr)
{
    asm volatile("ldmatrix.sync.aligned.m8n8.x4.trans.shared.b16 {%0,%1,%2,%3}, [%4];\n"
                 : "=r"(r0), "=r"(r1), "=r"(r2), "=r"(r3) : "r"(addr));
}
__device__ __forceinline__ void mma16816(float* c, const uint32_t* a, const uint32_t* b)
{
    asm volatile(
        "mma.sync.aligned.m16n8k16.row.col.f32.bf16.bf16.f32 "
        "{%0,%1,%2,%3}, {%4,%5,%6,%7}, {%8,%9}, {%0,%1,%2,%3};\n"
        : "+f"(c[0]), "+f"(c[1]), "+f"(c[2]), "+f"(c[3])
        : "r"(a[0]), "r"(a[1]), "r"(a[2]), "r"(a[3]), "r"(b[0]), "r"(b[1]));
}

// ---------------- expansion kernels ------------------------------------------
// Vectorized A-pattern: 8 k's per thread. in MxK -> out Mx3K [hi,hi,lo].
__global__ void expandA_kernel(const float* __restrict__ in, bf16* __restrict__ out, int K)
{
    int k0 = (blockIdx.x * 128 + threadIdx.x) * 8;
    int m  = blockIdx.y;
    const float4* ip = (const float4*)(in + (long)m * K + k0);
    float4 f0 = ip[0], f1 = ip[1];
    float v[8] = {f0.x, f0.y, f0.z, f0.w, f1.x, f1.y, f1.z, f1.w};
    unsigned short s[24];
#pragma unroll
    for (int j = 0; j < 8; j++) {
        bf16 hi, lo; split_bf16(v[j], hi, lo);
        unsigned short uh = __bfloat16_as_ushort(hi);
        unsigned short ul = __bfloat16_as_ushort(lo);
        s[3 * j] = uh; s[3 * j + 1] = uh; s[3 * j + 2] = ul;
    }
    uint32_t w[12];
#pragma unroll
    for (int i = 0; i < 12; i++)
        w[i] = (uint32_t)s[2 * i] | ((uint32_t)s[2 * i + 1] << 16);
    uint4* op = (uint4*)(out + (long)m * 3 * K + 3 * k0);
    op[0] = make_uint4(w[0], w[1], w[2], w[3]);
    op[1] = make_uint4(w[4], w[5], w[6], w[7]);
    op[2] = make_uint4(w[8], w[9], w[10], w[11]);
}

// B-pattern with column offset n0 (row stride ldn)
__global__ void expandB_kernel(const float* __restrict__ in, bf16* __restrict__ out,
                               int ldn, int n0, long sIn, long sOut)
{
    int n = n0 + blockIdx.x * 256 + threadIdx.x;
    int k = blockIdx.y;
    float x = in[(long)blockIdx.z * sIn + (long)k * ldn + n];
    bf16 hi, lo; split_bf16(x, hi, lo);
    bf16* o = out + (long)blockIdx.z * sOut + (long)(3 * k) * ldn + n;
    o[0] = hi; o[ldn] = lo; o[2 * ldn] = hi;
}

// cat expansion with time offset t0base (cols < 256 provably unused)
__global__ void expand_cat_kernel(const float* __restrict__ z0, const float* __restrict__ z1ss,
                                  int t0base)
{
    int t = t0base + blockIdx.x * 256 + threadIdx.x;
    int d = blockIdx.y;
    int b = blockIdx.z;
    float x = (t < MLEN) ? z0[((long)b * D_MODEL + d) * MLEN + t]
                         : z1ss[((long)b * D_MODEL + d) * QLEN + (t - MLEN)];
    bf16 hi, lo; split_bf16(x, hi, lo);
    bf16* o = g_cat3 + (long)b * 3 * D_MODEL * KLEN + (long)(3 * d) * KLEN + t;
    o[0] = hi; o[KLEN] = lo; o[2 * KLEN] = hi;
}

// ---------------- tensor-core GEMM (mma.sync), templated M-tile --------------
// GBM = 32*MI (MI=4 -> 128, MI=2 -> 64), GBN = 128, GBK = 64.
// mode: 0 = fp32 out, 1 = fp32 relu out, 2 = bf16-split([hi,lo,hi] rows) relu out
#define APADE 72     // A row length in elements (64 + 8 pad)
#define BPADE 136    // B row length in elements (128 + 8 pad)

template<int MI>
__global__ __launch_bounds__(256, 2)
void gemm_bf16_kernel(const bf16* __restrict__ A,
                      const bf16* __restrict__ B,
                      void*       __restrict__ Cv,
                      const float* __restrict__ bias,
                      const float* __restrict__ addend,
                      int K, int ldn,
                      long strideB, long strideC, long strideAdd,
                      int mode)
{
    extern __shared__ bf16 smem_g[];
    const int GBMt = 32 * MI;
    bf16* Asm = smem_g;                          // [2][GBMt*APADE]
    bf16* Bsm = smem_g + 2 * GBMt * APADE;       // [2][64*BPADE]

    const int tid  = threadIdx.x;
    const int lane = tid & 31;
    const int warp = tid >> 5;
    const int wm = warp >> 2;
    const int wn = warp & 3;
    const int bn = blockIdx.x * 128;
    const int bm = blockIdx.y * GBMt;

    const bf16* Ag = A + (long)bm * K;
    const bf16* Bg = B + (long)blockIdx.z * strideB;

    uint32_t sA = (uint32_t)__cvta_generic_to_shared(Asm);
    uint32_t sB = (uint32_t)__cvta_generic_to_shared(Bsm);
    const uint32_t sAsz = GBMt * APADE * 2;
    const uint32_t sBsz = 64 * BPADE * 2;

    float acc[MI][4][4];
#pragma unroll
    for (int i = 0; i < MI; i++)
#pragma unroll
        for (int j = 0; j < 4; j++)
#pragma unroll
            for (int r = 0; r < 4; r++) acc[i][j][r] = 0.f;

    auto load_tiles = [&](int buf, int k0) {
#pragma unroll
        for (int i = 0; i < MI; i++) {           // A: GBMt rows x 8 chunks
            int c   = tid + 256 * i;
            int row = c >> 3, ch = c & 7;
            cp_async16(sA + buf * sAsz + (row * APADE + ch * 8) * 2,
                       Ag + (long)row * K + k0 + ch * 8);
        }
#pragma unroll
        for (int i = 0; i < 4; i++) {            // B: 64 rows x 16 chunks
            int c   = tid + 256 * i;
            int row = c >> 4, ch = c & 15;
            cp_async16(sB + buf * sBsz + (row * BPADE + ch * 8) * 2,
                       Bg + (long)(k0 + row) * ldn + bn + ch * 8);
        }
        cp_commit();
    };

    load_tiles(0, 0);

    const int nIter = K >> 6;
    for (int it = 0; it < nIter; it++) {
        int buf = it & 1;
        cp_wait_all();
        __syncthreads();
        if (it + 1 < nIter) load_tiles(buf ^ 1, (it + 1) * 64);

#pragma unroll
        for (int ks = 0; ks < 4; ks++) {
            uint32_t afrag[MI][4];
            uint32_t bfrag[4][2];
            int lrow = lane & 15, lcol = (lane >> 4) * 8;
#pragma unroll
            for (int mi = 0; mi < MI; mi++) {
                uint32_t addr = sA + buf * sAsz +
                    ((MI * 16 * wm + 16 * mi + lrow) * APADE + ks * 16 + lcol) * 2;
                ldsm_x4(afrag[mi][0], afrag[mi][1], afrag[mi][2], afrag[mi][3], addr);
            }
#pragma unroll
            for (int nj2 = 0; nj2 < 2; nj2++) {
                uint32_t addr = sB + buf * sBsz +
                    ((ks * 16 + lrow) * BPADE + 32 * wn + 16 * nj2 + lcol) * 2;
                uint32_t r0, r1, r2, r3;
                ldsm_x4_t(r0, r1, r2, r3, addr);
                bfrag[2 * nj2][0] = r0;     bfrag[2 * nj2][1] = r1;
                bfrag[2 * nj2 + 1][0] = r2; bfrag[2 * nj2 + 1][1] = r3;
            }
#pragma unroll
            for (int mi = 0; mi < MI; mi++)
#pragma unroll
                for (int nj = 0; nj < 4; nj++)
                    mma16816(acc[mi][nj], afrag[mi], bfrag[nj]);
        }
        __syncthreads();
    }

    const float* Ad = addend ? (addend + (long)blockIdx.z * strideAdd) : nullptr;
    int g = lane >> 2, tg = lane & 3;

    if (mode == 2) {
        bf16* C3 = (bf16*)Cv + (long)blockIdx.z * strideC;
#pragma unroll
        for (int mi = 0; mi < MI; mi++) {
            int row0 = bm + MI * 16 * wm + 16 * mi + g;
            int row1 = row0 + 8;
            float bv0 = bias ? bias[row0] : 0.f;
            float bv1 = bias ? bias[row1] : 0.f;
#pragma unroll
            for (int nj = 0; nj < 4; nj++) {
                int col = bn + 32 * wn + 8 * nj + 2 * tg;
#pragma unroll
                for (int half = 0; half < 2; half++) {
                    int row = half ? row1 : row0;
                    float bv = half ? bv1 : bv0;
                    float v0 = fmaxf(acc[mi][nj][2 * half]     + bv, 0.f);
                    float v1 = fmaxf(acc[mi][nj][2 * half + 1] + bv, 0.f);
                    bf16 h0, l0, h1, l1;
                    split_bf16(v0, h0, l0);
                    split_bf16(v1, h1, l1);
                    long base = (long)(3 * row) * ldn + col;
                    C3[base]               = h0; C3[base + 1]           = h1;
                    C3[base + ldn]         = l0; C3[base + ldn + 1]     = l1;
                    C3[base + 2 * ldn]     = h0; C3[base + 2 * ldn + 1] = h1;
                }
            }
        }
        return;
    }

    float* Cb = (float*)Cv + (long)blockIdx.z * strideC;
#pragma unroll
    for (int mi = 0; mi < MI; mi++) {
        int row0 = bm + MI * 16 * wm + 16 * mi + g;
        int row1 = row0 + 8;
        float bv0 = bias ? bias[row0] : 0.f;
        float bv1 = bias ? bias[row1] : 0.f;
#pragma unroll
        for (int nj = 0; nj < 4; nj++) {
            int col = bn + 32 * wn + 8 * nj + 2 * tg;
            float v00 = acc[mi][nj][0] + bv0;
            float v01 = acc[mi][nj][1] + bv0;
            float v10 = acc[mi][nj][2] + bv1;
            float v11 = acc[mi][nj][3] + bv1;
            if (Ad) {
                v00 += Ad[(long)row0 * ldn + col];
                v01 += Ad[(long)row0 * ldn + col + 1];
                v10 += Ad[(long)row1 * ldn + col];
                v11 += Ad[(long)row1 * ldn + col + 1];
            }
            if (mode == 1) {
                v00 = fmaxf(v00, 0.f); v01 = fmaxf(v01, 0.f);
                v10 = fmaxf(v10, 0.f); v11 = fmaxf(v11, 0.f);
            }
            Cb[(long)row0 * ldn + col]     = v00;
            Cb[(long)row0 * ldn + col + 1] = v01;
            Cb[(long)row1 * ldn + col]     = v10;
            Cb[(long)row1 * ldn + col + 1] = v11;
        }
    }
}

// ---------------- tiled banded attention (writes bf16-split avec3) -----------
#define AT_SMEM ((64*65*2 + 64*258 + 64*260 + 4*64 + 64) * 4)

__global__ __launch_bounds__(256)
void attn_tiled_kernel(const float* __restrict__ wheads,
                       const float* __restrict__ rk,
                       const float* __restrict__ rwb,
                       const float* __restrict__ rrb,
                       bf16*        __restrict__ avec3)
{
    extern __shared__ float sm[];
    float* qw   = sm;                       // [qi][d]  stride 65
    float* qr   = qw  + 64 * 65;            // [qi][d]  stride 65
    float* BDs  = qr  + 64 * 65;            // [qi][t]  stride 258
    float* U    = BDs + 64 * 258;           // union region (64*260 floats)
    float* red  = U   + 64 * 260;
    float* sinv = red + 4 * 64;
    float* Rs = U;                          // [d][t]   stride 260 (phase 1)
    float* Ks = U;                          // [jj][d]  stride 65  (phase 2)
    float* Vs = U + 64 * 65;                // [jj][d]  stride 68 (16B-aligned rows)
    float* Ps = U + 64 * 65 + 64 * 68;      // [qi][jj] stride 65

    const int i0 = blockIdx.x * 64;
    const int h  = blockIdx.y;
    const int b  = blockIdx.z;
    const int tid = threadIdx.x;

    const float* W  = wheads + (long)b * (3 * D_MODEL) * KLEN;
    const float* Qg = W + (long)(h * DHEAD) * KLEN;
    const float* Kg = W + (long)(D_MODEL + h * DHEAD) * KLEN;
    const float* Vg = W + (long)(2 * D_MODEL + h * DHEAD) * KLEN;

    for (int idx = tid; idx < 64 * 64; idx += 256) {
        int d = idx >> 6, q = idx & 63;
        float qv = Qg[(long)d * KLEN + MLEN + i0 + q];
        qw[q * 65 + d] = qv + rwb[h * DHEAD + d];
        qr[q * 65 + d] = qv + rrb[h * DHEAD + d];
    }
    for (int idx = tid; idx < 64 * 256; idx += 256) {
        int d = idx >> 8, t = idx & 255;
        Rs[d * 260 + t] = rk[(long)(h * DHEAD + d) * KLEN + 768 + t];
    }
    __syncthreads();

    // phase 1: BD table, register-blocked (16 t's per pass)
    {
        int q = tid & 63, tg = tid >> 6;
#pragma unroll
        for (int g4 = 0; g4 < 4; g4++) {
            int t0 = tg * 64 + g4 * 16;
            float acc[16];
#pragma unroll
            for (int u = 0; u < 16; u++) acc[u] = 0.f;
            for (int d = 0; d < 64; d++) {
                float qv = qr[q * 65 + d];
                const float* rp = &Rs[d * 260 + t0];
#pragma unroll
                for (int u = 0; u < 16; u++)
                    acc[u] += qv * rp[u];
            }
#pragma unroll
            for (int u = 0; u < 16; u++)
                BDs[q * 258 + t0 + u] = acc[u];
        }
    }

    const int qi = tid & 63;
    const int jg = tid >> 6;
    float O[16];
#pragma unroll
    for (int u = 0; u < 16; u++) O[u] = 0.f;
    float sume = 0.f;

    for (int c = 0; c < 5; c++) {
        int jb = c * 64;
        __syncthreads();
        for (int idx = tid; idx < 64 * 64; idx += 256) {
            int d = idx >> 6, jj = idx & 63;
            int jglob = i0 + 257 + jb + jj;
            float kv = 0.f, vv = 0.f;
            if (jglob < KLEN) {
                kv = Kg[(long)d * KLEN + jglob];
                vv = Vg[(long)d * KLEN + jglob];
            }
            Ks[jj * 65 + d] = kv;
            Vs[jj * 68 + d] = vv;
        }
        __syncthreads();

        {
            float acc[16];
#pragma unroll
            for (int u = 0; u < 16; u++) acc[u] = 0.f;
#pragma unroll 8
            for (int d = 0; d < 64; d++) {
                float qv = qw[qi * 65 + d];
#pragma unroll
                for (int u = 0; u < 16; u++)
                    acc[u] += qv * Ks[(jg * 16 + u) * 65 + d];
            }
#pragma unroll
            for (int u = 0; u < 16; u++) {
                int jp = jb + jg * 16 + u;
                int t  = jp - qi;
                float pv = 0.f;
                if (t >= 0 && t < 256)
                    pv = __expf((acc[u] + BDs[qi * 258 + t]) * 0.125f);
                sume += pv;
                Ps[qi * 65 + jg * 16 + u] = pv;
            }
        }
        __syncthreads();

#pragma unroll 4
        for (int jj = 0; jj < 64; jj++) {
            float pv = Ps[qi * 65 + jj];
            const float* vp = &Vs[jj * 68 + jg * 16];
#pragma unroll
            for (int u = 0; u < 16; u++)
                O[u] += pv * vp[u];
        }
    }

    red[jg * 64 + qi] = sume;
    __syncthreads();
    if (tid < 64)
        sinv[tid] = 1.f / (red[tid] + red[64 + tid] + red[128 + tid] + red[192 + tid]);
    __syncthreads();
    float inv = sinv[qi];
    bf16* outp = avec3 + (long)b * 3 * D_MODEL * QLEN;
#pragma unroll
    for (int u = 0; u < 16; u++) {
        int dp = h * DHEAD + jg * 16 + u;
        float v = O[u] * inv;
        bf16 hi, lo; split_bf16(v, hi, lo);
        long base = (long)(3 * dp) * QLEN + i0 + qi;
        outp[base]            = hi;
        outp[base + QLEN]     = lo;
        outp[base + 2 * QLEN] = hi;
    }
}

// ---------------- channel LayerNorm (+ optional fused bf16-split out) --------
__global__ __launch_bounds__(256)
void ln_kernel(const float* __restrict__ y, float* __restrict__ out,
               bf16* __restrict__ out3)
{
    int b  = blockIdx.y;
    int t0 = blockIdx.x * 32;
    int tid = threadIdx.x;
    int tt = tid & 31, cg = tid >> 5;
    const float* Y = y + (long)b * D_MODEL * QLEN;

    float s = 0.f, s2 = 0.f;
    for (int c = cg * 128; c < cg * 128 + 128; c++) {
        float v = Y[(long)c * QLEN + t0 + tt];
        s += v; s2 += v * v;
    }
    __shared__ float ssum[8][32], ssq[8][32];
    __shared__ float smean[32], srstd[32];
    ssum[cg][tt] = s; ssq[cg][tt] = s2;
    __syncthreads();
    if (tid < 32) {
        float ts = 0.f, ts2 = 0.f;
#pragma unroll
        for (int g = 0; g < 8; g++) { ts += ssum[g][tid]; ts2 += ssq[g][tid]; }
        float mean = ts * (1.0f / D_MODEL);
        float var  = ts2 * (1.0f / D_MODEL) - mean * mean;
        smean[tid] = mean;
        srstd[tid] = rsqrtf(var + 1e-5f);
    }
    __syncthreads();
    float mean = smean[tt], rstd = srstd[tt];
    float* O = out + (long)b * D_MODEL * QLEN;
    bf16* O3 = out3 ? (out3 + (long)b * 3 * D_MODEL * QLEN) : nullptr;
    for (int c = cg * 128; c < cg * 128 + 128; c++) {
        float v = Y[(long)c * QLEN + t0 + tt];
        float r = (v - mean) * rstd;
        O[(long)c * QLEN + t0 + tt] = r;
        if (O3) {
            bf16 hi, lo; split_bf16(r, hi, lo);
            long base = (long)(3 * c) * QLEN + t0 + tt;
            O3[base]            = hi;
            O3[base + QLEN]     = lo;
            O3[base + 2 * QLEN] = hi;
        }
    }
}

// ---------------- launcher ---------------------------------------------------
#define GSMEM4 ((2 * 128 * APADE + 2 * 64 * BPADE) * 2)   // 71680
#define GSMEM2 ((2 * 64  * APADE + 2 * 64 * BPADE) * 2)   // 53248

extern "C" void kernel_launch(void* const* d_in, const int* in_sizes, int n_in,
                              void* d_out, int out_size)
{
    const float* z1ss    = (const float*)d_in[0];
    const float* uss     = (const float*)d_in[1];
    const float* z0      = (const float*)d_in[2];
    const float* pos_emb = (const float*)d_in[3];
    const float* qkv_w   = (const float*)d_in[4];
    const float* r_w     = (const float*)d_in[5];
    const float* r_w_bias= (const float*)d_in[6];
    const float* r_r_bias= (const float*)d_in[7];
    const float* o_w     = (const float*)d_in[8];
    const float* o_b     = (const float*)d_in[9];
    const float* ff1_w   = (const float*)d_in[10];
    const float* ff1_b   = (const float*)d_in[11];
    const float* ff2_w   = (const float*)d_in[12];
    const float* ff2_b   = (const float*)d_in[13];
    float* out = (float*)d_out;

    float *wheads, *rk, *tmp1, *x, *tmp2;
    bf16 *qkvw3, *rw3, *ow3, *ff1w3, *ff2w3, *pos3, *cat3, *avec3, *x3, *h3;
    cudaGetSymbolAddress((void**)&wheads, g_wheads);
    cudaGetSymbolAddress((void**)&rk,     g_rk);
    cudaGetSymbolAddress((void**)&tmp1,   g_tmp1);
    cudaGetSymbolAddress((void**)&x,      g_x);
    cudaGetSymbolAddress((void**)&tmp2,   g_tmp2);
    cudaGetSymbolAddress((void**)&qkvw3,  g_qkvw3);
    cudaGetSymbolAddress((void**)&rw3,    g_rw3);
    cudaGetSymbolAddress((void**)&ow3,    g_ow3);
    cudaGetSymbolAddress((void**)&ff1w3,  g_ff1w3);
    cudaGetSymbolAddress((void**)&ff2w3,  g_ff2w3);
    cudaGetSymbolAddress((void**)&pos3,   g_pos3);
    cudaGetSymbolAddress((void**)&cat3,   g_cat3);
    cudaGetSymbolAddress((void**)&avec3,  g_avec3);
    cudaGetSymbolAddress((void**)&x3,     g_x3);
    cudaGetSymbolAddress((void**)&h3,     g_h3);

    cudaFuncSetAttribute(attn_tiled_kernel,
                         cudaFuncAttributeMaxDynamicSharedMemorySize, AT_SMEM);
    cudaFuncSetAttribute(gemm_bf16_kernel<4>,
                         cudaFuncAttributeMaxDynamicSharedMemorySize, GSMEM4);
    cudaFuncSetAttribute(gemm_bf16_kernel<2>,
                         cudaFuncAttributeMaxDynamicSharedMemorySize, GSMEM2);

    const long s3dk = (long)3 * D_MODEL * KLEN;
    const long s3dq = (long)3 * D_MODEL * QLEN;
    const long sdq  = (long)D_MODEL * QLEN;

    // [0] qkv weight expansion (vectorized: 8 k/thread, 128 threads)
    expandA_kernel<<<dim3(1, 3 * D_MODEL), 128>>>(qkv_w, qkvw3, D_MODEL);
    // [1] cat expansion (cols [256,1024) only)
    expand_cat_kernel<<<dim3(3, D_MODEL, BSZ), 256>>>(z0, z1ss, 256);
    // [2..4]
    expandA_kernel<<<dim3(1, D_MODEL), 128>>>(r_w, rw3, D_MODEL);
    expandB_kernel<<<dim3(1, D_MODEL, 1), 256>>>(pos_emb, pos3, KLEN, 768, 0, 0);
    expandA_kernel<<<dim3(1, D_MODEL), 128>>>(o_w, ow3, D_MODEL);

    // [5] QKV over N-window [256,1024): M=3072, N=768 -> 576 CTAs
    gemm_bf16_kernel<4><<<dim3(6, 24, BSZ), 256, GSMEM4>>>(
        qkvw3, cat3 + 256, wheads + 256, nullptr, uss + 256,
        3 * D_MODEL, KLEN, s3dk, s3dk, s3dk, 0);

    expandA_kernel<<<dim3(1, DINNER), 128>>>(ff1_w, ff1w3, D_MODEL);
    expandA_kernel<<<dim3(4, D_MODEL), 128>>>(ff2_w, ff2w3, DINNER);

    // r_head_k: cols [768,1024) only; MI=2 for more CTAs (32)
    gemm_bf16_kernel<2><<<dim3(2, 16, 1), 256, GSMEM2>>>(
        rw3, pos3 + 768, rk + 768, nullptr, nullptr,
        3 * D_MODEL, KLEN, 0, 0, 0, 0);

    // banded attention -> avec3 (bf16 split, fused)
    attn_tiled_kernel<<<dim3(QLEN / 64, NHEAD, BSZ), 256, AT_SMEM>>>(
        wheads, rk, r_w_bias, r_r_bias, avec3);

    // O-proj: MI=2 -> 256 CTAs
    gemm_bf16_kernel<2><<<dim3(4, 16, BSZ), 256, GSMEM2>>>(
        ow3, avec3, tmp1, o_b, z1ss,
        3 * D_MODEL, QLEN, s3dq, sdq, sdq, 0);

    // x = LN(tmp1), fused x3
    ln_kernel<<<dim3(QLEN / 32, BSZ), 256>>>(tmp1, x, x3);

    // FF1: MI=4, 512 CTAs, fused bf16-split relu epilogue
    gemm_bf16_kernel<4><<<dim3(4, 32, BSZ), 256, GSMEM4>>>(
        ff1w3, x3, h3, ff1_b, nullptr,
        3 * D_MODEL, QLEN, s3dq, (long)3 * DINNER * QLEN, 0, 2);

    // FF2: MI=2 -> 256 CTAs
    gemm_bf16_kernel<2><<<dim3(4, 16, BSZ), 256, GSMEM2>>>(
        ff2w3, h3, tmp2, ff2_b, x,
        3 * DINNER, QLEN, (long)3 * DINNER * QLEN, sdq, sdq, 0);

    // out = LN(tmp2)
    ln_kernel<<<dim3(QLEN / 32, BSZ), 256>>>(tmp2, out, nullptr);
}